// round 12
// baseline (speedup 1.0000x reference)
#include <cuda_runtime.h>
#include <cuda_fp16.h>
#include <cstdint>

#define B_ROWS 8192
#define K_DIM  784
#define N_DIM  800
#define N_PAD  896
#define NSTEPS 25
#define STEP_ELEMS (B_ROWS * K_DIM)       // 6422528
#define Z_STEP  (B_ROWS * N_DIM)          // 6553600
#define WL_CAP  (1 << 20)
#define DELTA   1e-4f
#define NIT     49                        // single pass over K, 49 k16 tiles

// ---------------- device scratch ------------------------------------------
__device__ __half    g_sph[(size_t)NSTEPS * STEP_ELEMS];        // sp fp16
__device__ uint32_t  g_spc[(size_t)NSTEPS * STEP_ELEMS / 16];   // 2-bit codes
__device__ float     g_Z[(size_t)NSTEPS * Z_STEP];              // fast Z
__device__ float     g_S[Z_STEP];                               // spike counts
__device__ __half    g_w1s[2][(size_t)N_PAD * K_DIM];           // w1 fp16 splits
__device__ uint2     g_keys[NSTEPS];
__device__ int       g_cnt;
__device__ int       g_wl[WL_CAP];

// ---------------- threefry2x32 (matches JAX, 20 rounds) -------------------
__device__ __forceinline__ void threefry2x32(uint32_t k0, uint32_t k1,
                                             uint32_t x0, uint32_t x1,
                                             uint32_t &o0, uint32_t &o1) {
    uint32_t ks0 = k0, ks1 = k1, ks2 = 0x1BD11BDAu ^ k0 ^ k1;
    x0 += ks0; x1 += ks1;
#define TF_R(r) { x0 += x1; x1 = __funnelshift_l(x1, x1, (r)); x1 ^= x0; }
    TF_R(13) TF_R(15) TF_R(26) TF_R(6)
    x0 += ks1; x1 += ks2 + 1u;
    TF_R(17) TF_R(29) TF_R(16) TF_R(24)
    x0 += ks2; x1 += ks0 + 2u;
    TF_R(13) TF_R(15) TF_R(26) TF_R(6)
    x0 += ks0; x1 += ks1 + 3u;
    TF_R(17) TF_R(29) TF_R(16) TF_R(24)
    x0 += ks1; x1 += ks2 + 4u;
    TF_R(13) TF_R(15) TF_R(26) TF_R(6)
    x0 += ks2; x1 += ks0 + 5u;
#undef TF_R
    o0 = x0; o1 = x1;
}

__global__ void k_init() {
    int t = threadIdx.x;
    if (t < NSTEPS) {
        uint32_t o0, o1;
        threefry2x32(0u, 42u, 0u, (uint32_t)t, o0, o1);
        g_keys[t] = make_uint2(o0, o1);
    }
    if (t == 0) g_cnt = 0;
}

// ---------------- w1 -> 2 fp16 splits (exact power-of-2 scaled) ------------
// h0 = fp16(w * 2^9), h1 = fp16((w - h0*2^-9) * 2^20).  All scales exact.
// Z = 2^-9 * (S0 + 2^-11 * S1).  Rows >= 800 zero-padded.
__global__ void k_wsplit(const float* __restrict__ w1) {
    int idx = blockIdx.x * blockDim.x + threadIdx.x;
    if (idx >= N_PAD * K_DIM) return;
    int n = idx / K_DIM;
    float w = (n < N_DIM) ? w1[idx] : 0.0f;
    __half h0 = __float2half_rn(w * 512.0f);
    float r1 = w - __half2float(h0) * 0.001953125f;          // w - h0*2^-9
    __half h1 = __float2half_rn(r1 * 1048576.0f);            // * 2^20
    g_w1s[0][idx] = h0;
    g_w1s[1][idx] = h1;
}

// ---------------- spike generation: fp16 + 2-bit codes, 16 elems/thread ----
__global__ void k_spike_all(const float* __restrict__ inp) {
    const int t = blockIdx.y;
    const uint32_t e0 = (blockIdx.x * blockDim.x + threadIdx.x) * 16u;
    if (e0 >= STEP_ELEMS) return;
    const uint2 key = g_keys[t];
    float xv[16];
    #pragma unroll
    for (int v = 0; v < 4; v++)
        *(float4*)&xv[v * 4] = *(const float4*)(inp + e0 + v * 4);
    uint32_t codes = 0;
    __half sb[16];
    #pragma unroll
    for (int c = 0; c < 16; c++) {
        uint32_t o0, o1;
        threefry2x32(key.x, key.y, 0u, e0 + (uint32_t)c, o0, o1);
        uint32_t bits = o0 ^ o1;
        float r = __uint_as_float((bits >> 9) | 0x3f800000u) - 1.0f;
        float x = xv[c];
        uint32_t code = 1u;                          // sp = 0.5
        if (r * 2.0f <= fabsf(x)) {
            if (x > 0.0f)      code = 2u;            // sp = 1
            else if (x < 0.0f) code = 0u;            // sp = 0
        }
        codes |= code << (2 * c);
        unsigned short hb = code ? (unsigned short)(0x3400u + (code << 10)) : 0;
        sb[c] = __ushort_as_half(hb);                // 0 / 0.5 / 1 exact
    }
    size_t base = (size_t)t * STEP_ELEMS + e0;
    *(uint4*)(g_sph + base)     = *(uint4*)&sb[0];
    *(uint4*)(g_sph + base + 8) = *(uint4*)&sb[8];
    g_spc[base >> 4] = codes;
}

// ---------------- fast GEMM: single K pass, dual accumulators --------------
// Block 128M x 128N, 8 warps (2M x 4N), warp tile 64x32.
// Per k16 tile: load A once + both B splits; MMA into c0 (split0) and c1
// (split1).  Epilogue: Z = (c0 + 2^-11*c1) * 2^-9.
__device__ __forceinline__ void ldsm_x4(uint32_t* r, uint32_t addr) {
    asm volatile("ldmatrix.sync.aligned.m8n8.x4.shared.b16 {%0,%1,%2,%3}, [%4];"
                 : "=r"(r[0]), "=r"(r[1]), "=r"(r[2]), "=r"(r[3]) : "r"(addr));
}
__device__ __forceinline__ void mma16816(float* c, const uint32_t* a,
                                         uint32_t b0, uint32_t b1) {
    asm volatile(
        "mma.sync.aligned.m16n8k16.row.col.f32.f16.f16.f32 "
        "{%0,%1,%2,%3},{%4,%5,%6,%7},{%8,%9},{%0,%1,%2,%3};"
        : "+f"(c[0]), "+f"(c[1]), "+f"(c[2]), "+f"(c[3])
        : "r"(a[0]), "r"(a[1]), "r"(a[2]), "r"(a[3]), "r"(b0), "r"(b1));
}

#define TILE_A_SZ (128 * 48)
#define STAGE_SZ  (3 * TILE_A_SZ)          // A | B0 | B1

__global__ __launch_bounds__(256) void k_gemm_f() {
    __shared__ __align__(16) char smem[2 * STAGE_SZ];

    const int tid  = threadIdx.x;
    const int bx   = blockIdx.x;               // 0..6  (N, 128 each, pad 896)
    const int by   = blockIdx.y;               // 0..1599 (M, 128 each)
    const int warp = tid >> 5, lane = tid & 31;
    const int wm = (warp & 1) * 64;
    const int wn = (warp >> 1) * 32;

    const uint32_t sBase = (uint32_t)__cvta_generic_to_shared(smem);

    // LDSM source offsets within a stage (A at 0, B0 at 1*, B1 at 2*TILE_A_SZ)
    uint32_t offA[4], offB[2];
    {
        int rA = (lane & 7) + ((lane >> 3) & 1) * 8;
        int hA = lane >> 4;
        #pragma unroll
        for (int mi = 0; mi < 4; mi++)
            offA[mi] = (uint32_t)(wm + mi * 16 + rA) * 48 + hA * 16;
        int rB = (lane & 7) + ((lane >> 4) & 1) * 8;
        int hB = (lane >> 3) & 1;
        #pragma unroll
        for (int p = 0; p < 2; p++)
            offB[p] = TILE_A_SZ + (uint32_t)(wn + p * 16 + rB) * 48 + hB * 16;
    }

    const int rowL = tid >> 1;                 // 0..127 load row
    const int half = tid & 1;                  // 16B half of 32B row
    const __half* Abase = g_sph + (size_t)(by * 128) * K_DIM;
    const int bn = bx * 128;
    const size_t wOff = (size_t)(bn + rowL) * K_DIM;

    float c0[4][4][4], c1[4][4][4];
    #pragma unroll
    for (int mi = 0; mi < 4; mi++)
        #pragma unroll
        for (int ni = 0; ni < 4; ni++)
            #pragma unroll
            for (int q = 0; q < 4; q++) { c0[mi][ni][q] = 0.0f; c1[mi][ni][q] = 0.0f; }

    // prologue: tile 0
    uint4 av  = *(const uint4*)(Abase + (size_t)rowL * K_DIM + half * 8);
    uint4 bv0 = *(const uint4*)(g_w1s[0] + wOff + half * 8);
    uint4 bv1 = *(const uint4*)(g_w1s[1] + wOff + half * 8);
    *(uint4*)(smem + rowL * 48 + half * 16)                 = av;
    *(uint4*)(smem + TILE_A_SZ + rowL * 48 + half * 16)     = bv0;
    *(uint4*)(smem + 2 * TILE_A_SZ + rowL * 48 + half * 16) = bv1;
    __syncthreads();

    #pragma unroll 1
    for (int it = 0; it < NIT; it++) {
        const uint32_t sCur = sBase + (uint32_t)(it & 1) * STAGE_SZ;

        // prefetch tile it+1 into registers
        if (it + 1 < NIT) {
            const int k1 = (it + 1) * 16;
            av  = *(const uint4*)(Abase + (size_t)rowL * K_DIM + k1 + half * 8);
            bv0 = *(const uint4*)(g_w1s[0] + wOff + k1 + half * 8);
            bv1 = *(const uint4*)(g_w1s[1] + wOff + k1 + half * 8);
        }

        // compute on current stage: A frags once, both B splits
        uint32_t a[4][4], bf0[2][4], bf1[2][4];
        #pragma unroll
        for (int mi = 0; mi < 4; mi++) ldsm_x4(a[mi], sCur + offA[mi]);
        #pragma unroll
        for (int p = 0; p < 2; p++) {
            ldsm_x4(bf0[p], sCur + offB[p]);
            ldsm_x4(bf1[p], sCur + TILE_A_SZ + offB[p]);
        }
        #pragma unroll
        for (int mi = 0; mi < 4; mi++)
            #pragma unroll
            for (int ni = 0; ni < 4; ni++) {
                mma16816(c0[mi][ni], a[mi], bf0[ni >> 1][(ni & 1) * 2],
                         bf0[ni >> 1][(ni & 1) * 2 + 1]);
                mma16816(c1[mi][ni], a[mi], bf1[ni >> 1][(ni & 1) * 2],
                         bf1[ni >> 1][(ni & 1) * 2 + 1]);
            }

        // store next tile into the other stage; one barrier per tile
        if (it + 1 < NIT) {
            char* dst = smem + ((it + 1) & 1) * STAGE_SZ;
            *(uint4*)(dst + rowL * 48 + half * 16)                 = av;
            *(uint4*)(dst + TILE_A_SZ + rowL * 48 + half * 16)     = bv0;
            *(uint4*)(dst + 2 * TILE_A_SZ + rowL * 48 + half * 16) = bv1;
            __syncthreads();
        }
    }

    // store Z = 2^-9 * (c0 + 2^-11 * c1)  (guard padded cols)
    const int r0 = by * 128 + wm + (lane >> 2);
    const int cc0 = bn + wn + (lane & 3) * 2;
    #pragma unroll
    for (int mi = 0; mi < 4; mi++)
        #pragma unroll
        for (int ni = 0; ni < 4; ni++) {
            int col = cc0 + ni * 8;
            if (col < N_DIM) {
                int row = r0 + mi * 16;
                float z0 = __fmaf_rn(c1[mi][ni][0], 4.8828125e-4f, c0[mi][ni][0]);
                float z1 = __fmaf_rn(c1[mi][ni][1], 4.8828125e-4f, c0[mi][ni][1]);
                float z2 = __fmaf_rn(c1[mi][ni][2], 4.8828125e-4f, c0[mi][ni][2]);
                float z3 = __fmaf_rn(c1[mi][ni][3], 4.8828125e-4f, c0[mi][ni][3]);
                *(float2*)(g_Z + (size_t)row * N_DIM + col) =
                    make_float2(z0 * 0.001953125f, z1 * 0.001953125f);
                *(float2*)(g_Z + (size_t)(row + 8) * N_DIM + col) =
                    make_float2(z2 * 0.001953125f, z3 * 0.001953125f);
            }
        }
}

// ---------------- LIF + flagging (16 elems/thread, MLP-4 + prefetch) --------
__global__ void k_lif_flag() {
    const int q = blockIdx.x * blockDim.x + threadIdx.x;
    if (q >= Z_STEP / 16) return;
    const int idx = q * 16;
    const float cL = 0.95f;
    const float cI = 0.05000000074505806f;
    float m[16], cnt[16];
    unsigned flag = 0;
    #pragma unroll
    for (int h = 0; h < 16; h++) { m[h] = 0.0f; cnt[h] = 0.0f; }

    float4 z[4];
    #pragma unroll
    for (int v = 0; v < 4; v++)
        z[v] = *(const float4*)(g_Z + idx + v * 4);

    #pragma unroll 1
    for (int t = 0; t < NSTEPS; t++) {
        float4 zn[4];
        if (t + 1 < NSTEPS) {
            #pragma unroll
            for (int v = 0; v < 4; v++)
                zn[v] = *(const float4*)(g_Z + (size_t)(t + 1) * Z_STEP + idx + v * 4);
        }
        #pragma unroll
        for (int v = 0; v < 4; v++) {
            const float* zp = &z[v].x;
            #pragma unroll
            for (int u = 0; u < 4; u++) {
                int h = v * 4 + u;
                m[h] = __fadd_rn(__fmul_rn(cL, m[h]), __fmul_rn(cI, zp[u]));
                float thr = __fadd_rn(m[h], -1.0f);
                if (fabsf(thr) <= DELTA) flag |= 1u << h;
                if (thr > 0.0f) { cnt[h] += 1.0f; m[h] = __fadd_rn(m[h], -1.0f); }
            }
        }
        if (t + 1 < NSTEPS) {
            #pragma unroll
            for (int v = 0; v < 4; v++) z[v] = zn[v];
        }
    }
    #pragma unroll
    for (int v = 0; v < 4; v++)
        *(float4*)(g_S + idx + v * 4) =
            make_float4(cnt[v*4], cnt[v*4+1], cnt[v*4+2], cnt[v*4+3]);
    while (flag) {
        int h = __ffs(flag) - 1;
        flag &= flag - 1;
        int p = atomicAdd(&g_cnt, 1);
        if (p < WL_CAP) g_wl[p] = idx + h;
    }
}

// ---------------- exact recompute of flagged elements -----------------------
// Eigen kc=248 panel chains from 2-bit codes (validated fp32 ordering).
__global__ void k_exact(const float* __restrict__ w1) {
    const int i = blockIdx.x * blockDim.x + threadIdx.x;
    int n = g_cnt; if (n > WL_CAP) n = WL_CAP;
    if (i >= n) return;
    const int e = g_wl[i];
    const int b = e / N_DIM, j = e % N_DIM;
    const float* wrow = w1 + (size_t)j * K_DIM;
    const int pend[4] = {248, 496, 744, 784};
    const float cL = 0.95f;
    const float cI = 0.05000000074505806f;
    float m = 0.0f, cnt = 0.0f;
    #pragma unroll 1
    for (int t = 0; t < NSTEPS; t++) {
        const uint32_t* cw = g_spc + (((size_t)t * STEP_ELEMS + (size_t)b * K_DIM) >> 4);
        float csum = 0.0f;
        int k = 0;
        #pragma unroll 1
        for (int p = 0; p < 4; p++) {
            float acc = 0.0f;
            #pragma unroll 4
            for (; k < pend[p]; k++) {
                uint32_t code = (cw[k >> 4] >> ((k & 15) * 2)) & 3u;
                float sp = 0.5f * (float)code;
                acc = __fmaf_rn(sp, wrow[k], acc);
            }
            csum = __fadd_rn(csum, acc);
        }
        m = __fadd_rn(__fmul_rn(cL, m), __fmul_rn(cI, csum));
        float thr = __fadd_rn(m, -1.0f);
        if (thr > 0.0f) { cnt += 1.0f; m = __fadd_rn(m, -1.0f); }
    }
    g_S[e] = cnt;
}

// ---------------- final: out = (S @ w2^T) / 25 ------------------------------
__global__ void k_final(const float* __restrict__ w2, float* __restrict__ out) {
    int gw   = (blockIdx.x * blockDim.x + threadIdx.x) >> 5;
    int lane = threadIdx.x & 31;
    if (gw >= B_ROWS * 10) return;
    int b = gw / 10, c = gw % 10;
    const float* srow = g_S + (size_t)b * N_DIM;
    const float* wrow = w2 + (size_t)c * N_DIM;
    float s = 0.0f;
    for (int k = lane; k < N_DIM; k += 32) s += srow[k] * wrow[k];
    #pragma unroll
    for (int off = 16; off; off >>= 1) s += __shfl_xor_sync(0xFFFFFFFFu, s, off);
    if (lane == 0) out[(size_t)b * 10 + c] = s / 25.0f;
}

// ---------------- launch ----------------------------------------------------
extern "C" void kernel_launch(void* const* d_in, const int* in_sizes, int n_in,
                              void* d_out, int out_size) {
    const float* inp = (const float*)d_in[0];   // [8192, 784]
    const float* w1  = (const float*)d_in[1];   // [800, 784]
    const float* w2  = (const float*)d_in[2];   // [10, 800]
    float* out = (float*)d_out;                 // [8192, 10]

    k_init<<<1, 32>>>();
    k_wsplit<<<(N_PAD * K_DIM + 255) / 256, 256>>>(w1);
    k_spike_all<<<dim3(STEP_ELEMS / 16 / 256, NSTEPS), 256>>>(inp);
    k_gemm_f<<<dim3(7, 1600), 256>>>();
    k_lif_flag<<<(Z_STEP / 16 + 255) / 256, 256>>>();
    k_exact<<<WL_CAP / 256, 256>>>(w1);
    k_final<<<(B_ROWS * 10 * 32 + 255) / 256, 256>>>(w2, out);
}

// round 13
// speedup vs baseline: 1.1300x; 1.1300x over previous
#include <cuda_runtime.h>
#include <cuda_fp16.h>
#include <cstdint>

#define B_ROWS 8192
#define K_DIM  784
#define N_DIM  800
#define N_PAD  896
#define NSTEPS 25
#define STEP_ELEMS (B_ROWS * K_DIM)       // 6422528
#define Z_STEP  (B_ROWS * N_DIM)          // 6553600
#define WL_CAP  (1 << 20)
#define DELTA   1e-4f
#define NIT     98                        // 2 fp16-split passes x 49 k16 tiles
#define STAGES  3

// ---------------- device scratch ------------------------------------------
__device__ __align__(16) __half    g_sph[(size_t)NSTEPS * STEP_ELEMS];
__device__ uint32_t  g_spc[(size_t)NSTEPS * STEP_ELEMS / 16];   // 2-bit codes
__device__ float     g_Z[(size_t)NSTEPS * Z_STEP];              // fast Z
__device__ float     g_S[Z_STEP];                               // spike counts
__device__ __align__(16) __half    g_w1s[2][(size_t)N_PAD * K_DIM];
__device__ uint2     g_keys[NSTEPS];
__device__ int       g_cnt;
__device__ int       g_wl[WL_CAP];

// ---------------- threefry2x32 (matches JAX, 20 rounds) -------------------
__device__ __forceinline__ void threefry2x32(uint32_t k0, uint32_t k1,
                                             uint32_t x0, uint32_t x1,
                                             uint32_t &o0, uint32_t &o1) {
    uint32_t ks0 = k0, ks1 = k1, ks2 = 0x1BD11BDAu ^ k0 ^ k1;
    x0 += ks0; x1 += ks1;
#define TF_R(r) { x0 += x1; x1 = __funnelshift_l(x1, x1, (r)); x1 ^= x0; }
    TF_R(13) TF_R(15) TF_R(26) TF_R(6)
    x0 += ks1; x1 += ks2 + 1u;
    TF_R(17) TF_R(29) TF_R(16) TF_R(24)
    x0 += ks2; x1 += ks0 + 2u;
    TF_R(13) TF_R(15) TF_R(26) TF_R(6)
    x0 += ks0; x1 += ks1 + 3u;
    TF_R(17) TF_R(29) TF_R(16) TF_R(24)
    x0 += ks1; x1 += ks2 + 4u;
    TF_R(13) TF_R(15) TF_R(26) TF_R(6)
    x0 += ks2; x1 += ks0 + 5u;
#undef TF_R
    o0 = x0; o1 = x1;
}

__global__ void k_init() {
    int t = threadIdx.x;
    if (t < NSTEPS) {
        uint32_t o0, o1;
        threefry2x32(0u, 42u, 0u, (uint32_t)t, o0, o1);
        g_keys[t] = make_uint2(o0, o1);
    }
    if (t == 0) g_cnt = 0;
}

// ---------------- w1 -> 2 fp16 splits (exact power-of-2 scaled) ------------
__global__ void k_wsplit(const float* __restrict__ w1) {
    int idx = blockIdx.x * blockDim.x + threadIdx.x;
    if (idx >= N_PAD * K_DIM) return;
    int n = idx / K_DIM;
    float w = (n < N_DIM) ? w1[idx] : 0.0f;
    __half h0 = __float2half_rn(w * 512.0f);
    float r1 = w - __half2float(h0) * 0.001953125f;          // w - h0*2^-9
    __half h1 = __float2half_rn(r1 * 1048576.0f);            // * 2^20
    g_w1s[0][idx] = h0;
    g_w1s[1][idx] = h1;
}

// ---------------- spike generation: fp16 + 2-bit codes, 16 elems/thread ----
__global__ void k_spike_all(const float* __restrict__ inp) {
    const int t = blockIdx.y;
    const uint32_t e0 = (blockIdx.x * blockDim.x + threadIdx.x) * 16u;
    if (e0 >= STEP_ELEMS) return;
    const uint2 key = g_keys[t];
    float xv[16];
    #pragma unroll
    for (int v = 0; v < 4; v++)
        *(float4*)&xv[v * 4] = *(const float4*)(inp + e0 + v * 4);
    uint32_t codes = 0;
    __half sb[16];
    #pragma unroll
    for (int c = 0; c < 16; c++) {
        uint32_t o0, o1;
        threefry2x32(key.x, key.y, 0u, e0 + (uint32_t)c, o0, o1);
        uint32_t bits = o0 ^ o1;
        float r = __uint_as_float((bits >> 9) | 0x3f800000u) - 1.0f;
        float x = xv[c];
        uint32_t code = 1u;                          // sp = 0.5
        if (r * 2.0f <= fabsf(x)) {
            if (x > 0.0f)      code = 2u;            // sp = 1
            else if (x < 0.0f) code = 0u;            // sp = 0
        }
        codes |= code << (2 * c);
        unsigned short hb = code ? (unsigned short)(0x3400u + (code << 10)) : 0;
        sb[c] = __ushort_as_half(hb);                // 0 / 0.5 / 1 exact
    }
    size_t base = (size_t)t * STEP_ELEMS + e0;
    *(uint4*)(g_sph + base)     = *(uint4*)&sb[0];
    *(uint4*)(g_sph + base + 8) = *(uint4*)&sb[8];
    g_spc[base >> 4] = codes;
}

// ---------------- fast GEMM: 2 split passes, cp.async 3-stage pipeline -----
// Block 128M x 128N, 8 warps (2M x 4N), warp tile 64x32.
// Pass 0 = split[1] (x2^20); after it==48 rescale acc by 2^-11 (exact);
// pass 1 = split[0] (x2^9); epilogue scales by 2^-9.
__device__ __forceinline__ void ldsm_x4(uint32_t* r, uint32_t addr) {
    asm volatile("ldmatrix.sync.aligned.m8n8.x4.shared.b16 {%0,%1,%2,%3}, [%4];"
                 : "=r"(r[0]), "=r"(r[1]), "=r"(r[2]), "=r"(r[3]) : "r"(addr));
}
__device__ __forceinline__ void mma16816(float* c, const uint32_t* a,
                                         uint32_t b0, uint32_t b1) {
    asm volatile(
        "mma.sync.aligned.m16n8k16.row.col.f32.f16.f16.f32 "
        "{%0,%1,%2,%3},{%4,%5,%6,%7},{%8,%9},{%0,%1,%2,%3};"
        : "+f"(c[0]), "+f"(c[1]), "+f"(c[2]), "+f"(c[3])
        : "r"(a[0]), "r"(a[1]), "r"(a[2]), "r"(a[3]), "r"(b0), "r"(b1));
}
__device__ __forceinline__ void cp16(uint32_t smem_dst, const void* gsrc) {
    asm volatile("cp.async.cg.shared.global [%0], [%1], 16;"
                 :: "r"(smem_dst), "l"(gsrc) : "memory");
}
__device__ __forceinline__ void cp_commit() {
    asm volatile("cp.async.commit_group;" ::: "memory");
}
__device__ __forceinline__ void cp_wait1() {
    asm volatile("cp.async.wait_group 1;" ::: "memory");
}

#define TILE_A_SZ (128 * 48)
#define STAGE_SZ  (2 * TILE_A_SZ)          // A | B

__global__ __launch_bounds__(256, 2) void k_gemm_f() {
    __shared__ __align__(16) char smem[STAGES * STAGE_SZ];   // 36864 B

    const int tid  = threadIdx.x;
    const int bx   = blockIdx.x;               // 0..6  (N, 128 each, pad 896)
    const int by   = blockIdx.y;               // 0..1599 (M, 128 each)
    const int warp = tid >> 5, lane = tid & 31;
    const int wm = (warp & 1) * 64;
    const int wn = (warp >> 1) * 32;

    const uint32_t sBase = (uint32_t)__cvta_generic_to_shared(smem);

    // LDSM source offsets within a stage (A at 0, B at TILE_A_SZ)
    uint32_t offA[4], offB[2];
    {
        int rA = (lane & 7) + ((lane >> 3) & 1) * 8;
        int hA = lane >> 4;
        #pragma unroll
        for (int mi = 0; mi < 4; mi++)
            offA[mi] = (uint32_t)(wm + mi * 16 + rA) * 48 + hA * 16;
        int rB = (lane & 7) + ((lane >> 4) & 1) * 8;
        int hB = (lane >> 3) & 1;
        #pragma unroll
        for (int p = 0; p < 2; p++)
            offB[p] = TILE_A_SZ + (uint32_t)(wn + p * 16 + rB) * 48 + hB * 16;
    }

    const int rowL = tid >> 1;                 // 0..127 load row
    const int half = tid & 1;                  // 16B half of 32B row
    const __half* Abase = g_sph + (size_t)(by * 128) * K_DIM
                                + (size_t)rowL * K_DIM + half * 8;
    const int bn = bx * 128;
    const size_t wOff = (size_t)(bn + rowL) * K_DIM + half * 8;
    const uint32_t dOff = (uint32_t)rowL * 48 + half * 16;

    float c[4][4][4];
    #pragma unroll
    for (int mi = 0; mi < 4; mi++)
        #pragma unroll
        for (int ni = 0; ni < 4; ni++)
            #pragma unroll
            for (int q = 0; q < 4; q++) c[mi][ni][q] = 0.0f;

    // issue loads for logical tile `it` into stage it % STAGES
    auto issue = [&](int it) {
        const int sel = (it < 49) ? 1 : 0;
        const int kt  = (it < 49) ? it : it - 49;
        const uint32_t st = sBase + (uint32_t)(it % STAGES) * STAGE_SZ;
        cp16(st + dOff, Abase + kt * 16);
        cp16(st + TILE_A_SZ + dOff, g_w1s[sel] + wOff + kt * 16);
    };

    // prologue: stages 0 and 1 in flight
    issue(0); cp_commit();
    issue(1); cp_commit();

    #pragma unroll 1
    for (int it = 0; it < NIT; it++) {
        cp_wait1();                      // group `it` complete (≤1 pending)
        __syncthreads();                 // all threads' tiles visible

        const uint32_t sCur = sBase + (uint32_t)(it % STAGES) * STAGE_SZ;
        uint32_t a[4][4], bf[2][4];
        #pragma unroll
        for (int mi = 0; mi < 4; mi++) ldsm_x4(a[mi], sCur + offA[mi]);
        #pragma unroll
        for (int p = 0; p < 2; p++)    ldsm_x4(bf[p], sCur + offB[p]);
        #pragma unroll
        for (int mi = 0; mi < 4; mi++)
            #pragma unroll
            for (int ni = 0; ni < 4; ni++)
                mma16816(c[mi][ni], a[mi], bf[ni >> 1][(ni & 1) * 2],
                         bf[ni >> 1][(ni & 1) * 2 + 1]);

        // end of split-1 pass: rescale accumulator by 2^-11 (exact)
        if (it == 48) {
            #pragma unroll
            for (int mi = 0; mi < 4; mi++)
                #pragma unroll
                for (int ni = 0; ni < 4; ni++)
                    #pragma unroll
                    for (int q = 0; q < 4; q++)
                        c[mi][ni][q] *= 4.8828125e-4f;
        }

        // issue tile it+2 (overwrites stage (it-1)%3 — compute(it-1) done
        // before this iteration's barrier, so safe)
        if (it + 2 < NIT) issue(it + 2);
        cp_commit();
    }

    // store Z = 2^-9 * c  (guard padded cols)
    const int r0 = by * 128 + wm + (lane >> 2);
    const int cc0 = bn + wn + (lane & 3) * 2;
    #pragma unroll
    for (int mi = 0; mi < 4; mi++)
        #pragma unroll
        for (int ni = 0; ni < 4; ni++) {
            int col = cc0 + ni * 8;
            if (col < N_DIM) {
                int row = r0 + mi * 16;
                *(float2*)(g_Z + (size_t)row * N_DIM + col) =
                    make_float2(c[mi][ni][0] * 0.001953125f,
                                c[mi][ni][1] * 0.001953125f);
                *(float2*)(g_Z + (size_t)(row + 8) * N_DIM + col) =
                    make_float2(c[mi][ni][2] * 0.001953125f,
                                c[mi][ni][3] * 0.001953125f);
            }
        }
}

// ---------------- LIF + flagging (16 elems/thread, MLP-4 + prefetch) --------
__global__ void k_lif_flag() {
    const int q = blockIdx.x * blockDim.x + threadIdx.x;
    if (q >= Z_STEP / 16) return;
    const int idx = q * 16;
    const float cL = 0.95f;
    const float cI = 0.05000000074505806f;
    float m[16], cnt[16];
    unsigned flag = 0;
    #pragma unroll
    for (int h = 0; h < 16; h++) { m[h] = 0.0f; cnt[h] = 0.0f; }

    float4 z[4];
    #pragma unroll
    for (int v = 0; v < 4; v++)
        z[v] = *(const float4*)(g_Z + idx + v * 4);

    #pragma unroll 1
    for (int t = 0; t < NSTEPS; t++) {
        float4 zn[4];
        if (t + 1 < NSTEPS) {
            #pragma unroll
            for (int v = 0; v < 4; v++)
                zn[v] = *(const float4*)(g_Z + (size_t)(t + 1) * Z_STEP + idx + v * 4);
        }
        #pragma unroll
        for (int v = 0; v < 4; v++) {
            const float* zp = &z[v].x;
            #pragma unroll
            for (int u = 0; u < 4; u++) {
                int h = v * 4 + u;
                m[h] = __fadd_rn(__fmul_rn(cL, m[h]), __fmul_rn(cI, zp[u]));
                float thr = __fadd_rn(m[h], -1.0f);
                if (fabsf(thr) <= DELTA) flag |= 1u << h;
                if (thr > 0.0f) { cnt[h] += 1.0f; m[h] = __fadd_rn(m[h], -1.0f); }
            }
        }
        if (t + 1 < NSTEPS) {
            #pragma unroll
            for (int v = 0; v < 4; v++) z[v] = zn[v];
        }
    }
    #pragma unroll
    for (int v = 0; v < 4; v++)
        *(float4*)(g_S + idx + v * 4) =
            make_float4(cnt[v*4], cnt[v*4+1], cnt[v*4+2], cnt[v*4+3]);
    while (flag) {
        int h = __ffs(flag) - 1;
        flag &= flag - 1;
        int p = atomicAdd(&g_cnt, 1);
        if (p < WL_CAP) g_wl[p] = idx + h;
    }
}

// ---------------- exact recompute of flagged elements (grid-stride) ---------
__global__ void k_exact(const float* __restrict__ w1) {
    int n = g_cnt; if (n > WL_CAP) n = WL_CAP;
    const int stride = gridDim.x * blockDim.x;
    for (int i = blockIdx.x * blockDim.x + threadIdx.x; i < n; i += stride) {
        const int e = g_wl[i];
        const int b = e / N_DIM, j = e % N_DIM;
        const float* wrow = w1 + (size_t)j * K_DIM;
        const int pend[4] = {248, 496, 744, 784};
        const float cL = 0.95f;
        const float cI = 0.05000000074505806f;
        float m = 0.0f, cnt = 0.0f;
        #pragma unroll 1
        for (int t = 0; t < NSTEPS; t++) {
            const uint32_t* cw = g_spc + (((size_t)t * STEP_ELEMS + (size_t)b * K_DIM) >> 4);
            float csum = 0.0f;
            int k = 0;
            #pragma unroll 1
            for (int p = 0; p < 4; p++) {
                float acc = 0.0f;
                #pragma unroll 4
                for (; k < pend[p]; k++) {
                    uint32_t code = (cw[k >> 4] >> ((k & 15) * 2)) & 3u;
                    float sp = 0.5f * (float)code;
                    acc = __fmaf_rn(sp, wrow[k], acc);
                }
                csum = __fadd_rn(csum, acc);
            }
            m = __fadd_rn(__fmul_rn(cL, m), __fmul_rn(cI, csum));
            float thr = __fadd_rn(m, -1.0f);
            if (thr > 0.0f) { cnt += 1.0f; m = __fadd_rn(m, -1.0f); }
        }
        g_S[e] = cnt;
    }
}

// ---------------- final: out = (S @ w2^T) / 25 ------------------------------
__global__ void k_final(const float* __restrict__ w2, float* __restrict__ out) {
    int gw   = (blockIdx.x * blockDim.x + threadIdx.x) >> 5;
    int lane = threadIdx.x & 31;
    if (gw >= B_ROWS * 10) return;
    int b = gw / 10, c = gw % 10;
    const float* srow = g_S + (size_t)b * N_DIM;
    const float* wrow = w2 + (size_t)c * N_DIM;
    float s = 0.0f;
    for (int k = lane; k < N_DIM; k += 32) s += srow[k] * wrow[k];
    #pragma unroll
    for (int off = 16; off; off >>= 1) s += __shfl_xor_sync(0xFFFFFFFFu, s, off);
    if (lane == 0) out[(size_t)b * 10 + c] = s / 25.0f;
}

// ---------------- launch ----------------------------------------------------
extern "C" void kernel_launch(void* const* d_in, const int* in_sizes, int n_in,
                              void* d_out, int out_size) {
    const float* inp = (const float*)d_in[0];   // [8192, 784]
    const float* w1  = (const float*)d_in[1];   // [800, 784]
    const float* w2  = (const float*)d_in[2];   // [10, 800]
    float* out = (float*)d_out;                 // [8192, 10]

    k_init<<<1, 32>>>();
    k_wsplit<<<(N_PAD * K_DIM + 255) / 256, 256>>>(w1);
    k_spike_all<<<dim3(STEP_ELEMS / 16 / 256, NSTEPS), 256>>>(inp);
    k_gemm_f<<<dim3(7, 1600), 256>>>();
    k_lif_flag<<<(Z_STEP / 16 + 255) / 256, 256>>>();
    k_exact<<<512, 256>>>(w1);
    k_final<<<(B_ROWS * 10 * 32 + 255) / 256, 256>>>(w2, out);
}

// round 14
// speedup vs baseline: 1.2110x; 1.0717x over previous
#include <cuda_runtime.h>
#include <cuda_fp16.h>
#include <cstdint>

#define B_ROWS 8192
#define K_DIM  784
#define N_DIM  800
#define NSTEPS 25
#define STEP_ELEMS (B_ROWS * K_DIM)       // 6422528
#define Z_STEP  (B_ROWS * N_DIM)          // 6553600
#define WL_CAP  (1 << 20)
#define DELTA   1e-4f
#define NIT     98                        // 2 fp16-split passes x 49 k16 tiles
#define STAGES  3
#define NT      160                       // N tile (800 = 5 x 160, no padding)

// ---------------- device scratch ------------------------------------------
__device__ __align__(16) __half    g_sph[(size_t)NSTEPS * STEP_ELEMS];
__device__ uint32_t  g_spc[(size_t)NSTEPS * STEP_ELEMS / 16];   // 2-bit codes
__device__ float     g_Z[(size_t)NSTEPS * Z_STEP];              // fast Z
__device__ float     g_S[Z_STEP];                               // spike counts
__device__ __align__(16) __half    g_w1s[2][(size_t)N_DIM * K_DIM];
__device__ uint2     g_keys[NSTEPS];
__device__ int       g_cnt;
__device__ int       g_wl[WL_CAP];

// ---------------- threefry2x32 (matches JAX, 20 rounds) -------------------
__device__ __forceinline__ void threefry2x32(uint32_t k0, uint32_t k1,
                                             uint32_t x0, uint32_t x1,
                                             uint32_t &o0, uint32_t &o1) {
    uint32_t ks0 = k0, ks1 = k1, ks2 = 0x1BD11BDAu ^ k0 ^ k1;
    x0 += ks0; x1 += ks1;
#define TF_R(r) { x0 += x1; x1 = __funnelshift_l(x1, x1, (r)); x1 ^= x0; }
    TF_R(13) TF_R(15) TF_R(26) TF_R(6)
    x0 += ks1; x1 += ks2 + 1u;
    TF_R(17) TF_R(29) TF_R(16) TF_R(24)
    x0 += ks2; x1 += ks0 + 2u;
    TF_R(13) TF_R(15) TF_R(26) TF_R(6)
    x0 += ks0; x1 += ks1 + 3u;
    TF_R(17) TF_R(29) TF_R(16) TF_R(24)
    x0 += ks1; x1 += ks2 + 4u;
    TF_R(13) TF_R(15) TF_R(26) TF_R(6)
    x0 += ks2; x1 += ks0 + 5u;
#undef TF_R
    o0 = x0; o1 = x1;
}

__global__ void k_init() {
    int t = threadIdx.x;
    if (t < NSTEPS) {
        uint32_t o0, o1;
        threefry2x32(0u, 42u, 0u, (uint32_t)t, o0, o1);
        g_keys[t] = make_uint2(o0, o1);
    }
    if (t == 0) g_cnt = 0;
}

// ---------------- w1 -> 2 fp16 splits (exact power-of-2 scaled) ------------
__global__ void k_wsplit(const float* __restrict__ w1) {
    int idx = blockIdx.x * blockDim.x + threadIdx.x;
    if (idx >= N_DIM * K_DIM) return;
    float w = w1[idx];
    __half h0 = __float2half_rn(w * 512.0f);
    float r1 = w - __half2float(h0) * 0.001953125f;          // w - h0*2^-9
    __half h1 = __float2half_rn(r1 * 1048576.0f);            // * 2^20
    g_w1s[0][idx] = h0;
    g_w1s[1][idx] = h1;
}

// ---------------- spike generation: fp16 + 2-bit codes, 16 elems/thread ----
__global__ void k_spike_all(const float* __restrict__ inp) {
    const int t = blockIdx.y;
    const uint32_t e0 = (blockIdx.x * blockDim.x + threadIdx.x) * 16u;
    if (e0 >= STEP_ELEMS) return;
    const uint2 key = g_keys[t];
    float xv[16];
    #pragma unroll
    for (int v = 0; v < 4; v++)
        *(float4*)&xv[v * 4] = *(const float4*)(inp + e0 + v * 4);
    uint32_t codes = 0;
    __half sb[16];
    #pragma unroll
    for (int c = 0; c < 16; c++) {
        uint32_t o0, o1;
        threefry2x32(key.x, key.y, 0u, e0 + (uint32_t)c, o0, o1);
        uint32_t bits = o0 ^ o1;
        float r = __uint_as_float((bits >> 9) | 0x3f800000u) - 1.0f;
        float x = xv[c];
        uint32_t code = 1u;                          // sp = 0.5
        if (r * 2.0f <= fabsf(x)) {
            if (x > 0.0f)      code = 2u;            // sp = 1
            else if (x < 0.0f) code = 0u;            // sp = 0
        }
        codes |= code << (2 * c);
        unsigned short hb = code ? (unsigned short)(0x3400u + (code << 10)) : 0;
        sb[c] = __ushort_as_half(hb);                // 0 / 0.5 / 1 exact
    }
    size_t base = (size_t)t * STEP_ELEMS + e0;
    *(uint4*)(g_sph + base)     = *(uint4*)&sb[0];
    *(uint4*)(g_sph + base + 8) = *(uint4*)&sb[8];
    g_spc[base >> 4] = codes;
}

// ---------------- fast GEMM: 128M x 160N tiles, cp.async 3-stage -----------
// 8 warps (2M x 4N), warp tile 64x40 -> 20 MMAs per k16 tile, no N padding.
// Pass 0 = split[1] (x2^20); after it==48 rescale acc by 2^-11 (exact);
// pass 1 = split[0] (x2^9); epilogue scales by 2^-9.
__device__ __forceinline__ void ldsm_x4(uint32_t* r, uint32_t addr) {
    asm volatile("ldmatrix.sync.aligned.m8n8.x4.shared.b16 {%0,%1,%2,%3}, [%4];"
                 : "=r"(r[0]), "=r"(r[1]), "=r"(r[2]), "=r"(r[3]) : "r"(addr));
}
__device__ __forceinline__ void ldsm_x2(uint32_t* r, uint32_t addr) {
    asm volatile("ldmatrix.sync.aligned.m8n8.x2.shared.b16 {%0,%1}, [%2];"
                 : "=r"(r[0]), "=r"(r[1]) : "r"(addr));
}
__device__ __forceinline__ void mma16816(float* c, const uint32_t* a,
                                         uint32_t b0, uint32_t b1) {
    asm volatile(
        "mma.sync.aligned.m16n8k16.row.col.f32.f16.f16.f32 "
        "{%0,%1,%2,%3},{%4,%5,%6,%7},{%8,%9},{%0,%1,%2,%3};"
        : "+f"(c[0]), "+f"(c[1]), "+f"(c[2]), "+f"(c[3])
        : "r"(a[0]), "r"(a[1]), "r"(a[2]), "r"(a[3]), "r"(b0), "r"(b1));
}
__device__ __forceinline__ void cp16(uint32_t smem_dst, const void* gsrc) {
    asm volatile("cp.async.cg.shared.global [%0], [%1], 16;"
                 :: "r"(smem_dst), "l"(gsrc) : "memory");
}
__device__ __forceinline__ void cp_commit() {
    asm volatile("cp.async.commit_group;" ::: "memory");
}
__device__ __forceinline__ void cp_wait1() {
    asm volatile("cp.async.wait_group 1;" ::: "memory");
}

#define TILE_A_SZ (128 * 48)               // 6144
#define TILE_B_SZ (NT * 48)                // 7680
#define STAGE_SZ  (TILE_A_SZ + TILE_B_SZ)  // 13824

__global__ __launch_bounds__(256, 2) void k_gemm_f() {
    __shared__ __align__(16) char smem[STAGES * STAGE_SZ];   // 41472 B

    const int tid  = threadIdx.x;
    const int bx   = blockIdx.x;               // 0..4  (N, 160 each)
    const int by   = blockIdx.y;               // 0..1599 (M, 128 each)
    const int warp = tid >> 5, lane = tid & 31;
    const int wm = (warp & 1) * 64;
    const int wn = (warp >> 1) * 40;

    const uint32_t sBase = (uint32_t)__cvta_generic_to_shared(smem);

    // LDSM source offsets within a stage (A at 0, B at TILE_A_SZ)
    uint32_t offA[4], offB4[2], offB2;
    {
        int rA = (lane & 7) + ((lane >> 3) & 1) * 8;
        int hA = lane >> 4;
        #pragma unroll
        for (int mi = 0; mi < 4; mi++)
            offA[mi] = (uint32_t)(wm + mi * 16 + rA) * 48 + hA * 16;
        int rB = (lane & 7) + ((lane >> 4) & 1) * 8;
        int hB = (lane >> 3) & 1;
        #pragma unroll
        for (int p = 0; p < 2; p++)
            offB4[p] = TILE_A_SZ + (uint32_t)(wn + p * 16 + rB) * 48 + hB * 16;
        int rB2 = lane & 7;                      // lanes 0-15 used by x2
        int hB2 = (lane >> 3) & 1;
        offB2 = TILE_A_SZ + (uint32_t)(wn + 32 + rB2) * 48 + hB2 * 16;
    }

    const int rowL = tid >> 1;                 // 0..127
    const int half = tid & 1;
    const __half* Abase = g_sph + (size_t)(by * 128) * K_DIM
                                + (size_t)rowL * K_DIM + half * 8;
    const int bn = bx * NT;
    const size_t wOff0 = (size_t)(bn + rowL) * K_DIM + half * 8;
    const size_t wOff1 = (size_t)(bn + 128 + rowL) * K_DIM + half * 8;  // tid<64
    const uint32_t dOffA  = (uint32_t)rowL * 48 + half * 16;
    const uint32_t dOffB0 = TILE_A_SZ + (uint32_t)rowL * 48 + half * 16;
    const uint32_t dOffB1 = TILE_A_SZ + (uint32_t)(128 + rowL) * 48 + half * 16;

    float c[4][5][4];
    #pragma unroll
    for (int mi = 0; mi < 4; mi++)
        #pragma unroll
        for (int ni = 0; ni < 5; ni++)
            #pragma unroll
            for (int q = 0; q < 4; q++) c[mi][ni][q] = 0.0f;

    auto issue = [&](int it) {
        const int sel = (it < 49) ? 1 : 0;
        const int kt  = (it < 49) ? it : it - 49;
        const uint32_t st = sBase + (uint32_t)(it % STAGES) * STAGE_SZ;
        cp16(st + dOffA, Abase + kt * 16);
        cp16(st + dOffB0, g_w1s[sel] + wOff0 + kt * 16);
        if (tid < 64)
            cp16(st + dOffB1, g_w1s[sel] + wOff1 + kt * 16);
    };

    issue(0); cp_commit();
    issue(1); cp_commit();

    #pragma unroll 1
    for (int it = 0; it < NIT; it++) {
        cp_wait1();
        __syncthreads();

        const uint32_t sCur = sBase + (uint32_t)(it % STAGES) * STAGE_SZ;
        uint32_t a[4][4], bf[2][4], b2[2];
        #pragma unroll
        for (int mi = 0; mi < 4; mi++) ldsm_x4(a[mi], sCur + offA[mi]);
        #pragma unroll
        for (int p = 0; p < 2; p++)    ldsm_x4(bf[p], sCur + offB4[p]);
        ldsm_x2(b2, sCur + offB2);
        #pragma unroll
        for (int mi = 0; mi < 4; mi++) {
            #pragma unroll
            for (int ni = 0; ni < 4; ni++)
                mma16816(c[mi][ni], a[mi], bf[ni >> 1][(ni & 1) * 2],
                         bf[ni >> 1][(ni & 1) * 2 + 1]);
            mma16816(c[mi][4], a[mi], b2[0], b2[1]);
        }

        if (it == 48) {                  // end of split-1 pass: x2^-11 (exact)
            #pragma unroll
            for (int mi = 0; mi < 4; mi++)
                #pragma unroll
                for (int ni = 0; ni < 5; ni++)
                    #pragma unroll
                    for (int q = 0; q < 4; q++)
                        c[mi][ni][q] *= 4.8828125e-4f;
        }

        if (it + 2 < NIT) issue(it + 2);
        cp_commit();
    }

    // store Z = 2^-9 * c  (no guards: 5*160 = 800 exactly)
    const int r0 = by * 128 + wm + (lane >> 2);
    const int cc0 = bn + wn + (lane & 3) * 2;
    #pragma unroll
    for (int mi = 0; mi < 4; mi++)
        #pragma unroll
        for (int ni = 0; ni < 5; ni++) {
            int col = cc0 + ni * 8;
            int row = r0 + mi * 16;
            *(float2*)(g_Z + (size_t)row * N_DIM + col) =
                make_float2(c[mi][ni][0] * 0.001953125f,
                            c[mi][ni][1] * 0.001953125f);
            *(float2*)(g_Z + (size_t)(row + 8) * N_DIM + col) =
                make_float2(c[mi][ni][2] * 0.001953125f,
                            c[mi][ni][3] * 0.001953125f);
        }
}

// ---------------- LIF + flagging (16 elems/thread, MLP-4 + prefetch) --------
__global__ void k_lif_flag() {
    const int q = blockIdx.x * blockDim.x + threadIdx.x;
    if (q >= Z_STEP / 16) return;
    const int idx = q * 16;
    const float cL = 0.95f;
    const float cI = 0.05000000074505806f;
    float m[16], cnt[16];
    unsigned flag = 0;
    #pragma unroll
    for (int h = 0; h < 16; h++) { m[h] = 0.0f; cnt[h] = 0.0f; }

    float4 z[4];
    #pragma unroll
    for (int v = 0; v < 4; v++)
        z[v] = *(const float4*)(g_Z + idx + v * 4);

    #pragma unroll 1
    for (int t = 0; t < NSTEPS; t++) {
        float4 zn[4];
        if (t + 1 < NSTEPS) {
            #pragma unroll
            for (int v = 0; v < 4; v++)
                zn[v] = *(const float4*)(g_Z + (size_t)(t + 1) * Z_STEP + idx + v * 4);
        }
        #pragma unroll
        for (int v = 0; v < 4; v++) {
            const float* zp = &z[v].x;
            #pragma unroll
            for (int u = 0; u < 4; u++) {
                int h = v * 4 + u;
                m[h] = __fadd_rn(__fmul_rn(cL, m[h]), __fmul_rn(cI, zp[u]));
                float thr = __fadd_rn(m[h], -1.0f);
                if (fabsf(thr) <= DELTA) flag |= 1u << h;
                if (thr > 0.0f) { cnt[h] += 1.0f; m[h] = __fadd_rn(m[h], -1.0f); }
            }
        }
        if (t + 1 < NSTEPS) {
            #pragma unroll
            for (int v = 0; v < 4; v++) z[v] = zn[v];
        }
    }
    #pragma unroll
    for (int v = 0; v < 4; v++)
        *(float4*)(g_S + idx + v * 4) =
            make_float4(cnt[v*4], cnt[v*4+1], cnt[v*4+2], cnt[v*4+3]);
    while (flag) {
        int h = __ffs(flag) - 1;
        flag &= flag - 1;
        int p = atomicAdd(&g_cnt, 1);
        if (p < WL_CAP) g_wl[p] = idx + h;
    }
}

// ---------------- exact recompute of flagged elements (grid-stride) ---------
__global__ void k_exact(const float* __restrict__ w1) {
    int n = g_cnt; if (n > WL_CAP) n = WL_CAP;
    const int stride = gridDim.x * blockDim.x;
    for (int i = blockIdx.x * blockDim.x + threadIdx.x; i < n; i += stride) {
        const int e = g_wl[i];
        const int b = e / N_DIM, j = e % N_DIM;
        const float* wrow = w1 + (size_t)j * K_DIM;
        const int pend[4] = {248, 496, 744, 784};
        const float cL = 0.95f;
        const float cI = 0.05000000074505806f;
        float m = 0.0f, cnt = 0.0f;
        #pragma unroll 1
        for (int t = 0; t < NSTEPS; t++) {
            const uint32_t* cw = g_spc + (((size_t)t * STEP_ELEMS + (size_t)b * K_DIM) >> 4);
            float csum = 0.0f;
            int k = 0;
            #pragma unroll 1
            for (int p = 0; p < 4; p++) {
                float acc = 0.0f;
                #pragma unroll 4
                for (; k < pend[p]; k++) {
                    uint32_t code = (cw[k >> 4] >> ((k & 15) * 2)) & 3u;
                    float sp = 0.5f * (float)code;
                    acc = __fmaf_rn(sp, wrow[k], acc);
                }
                csum = __fadd_rn(csum, acc);
            }
            m = __fadd_rn(__fmul_rn(cL, m), __fmul_rn(cI, csum));
            float thr = __fadd_rn(m, -1.0f);
            if (thr > 0.0f) { cnt += 1.0f; m = __fadd_rn(m, -1.0f); }
        }
        g_S[e] = cnt;
    }
}

// ---------------- final: one warp per row, all 10 classes -------------------
// Per-class arithmetic identical to the old per-(b,c) kernel (same lane-stride
// partials + same shfl reduction) -> bit-identical output, S read once.
__global__ void k_final(const float* __restrict__ w2, float* __restrict__ out) {
    int b    = (blockIdx.x * blockDim.x + threadIdx.x) >> 5;
    int lane = threadIdx.x & 31;
    if (b >= B_ROWS) return;
    const float* srow = g_S + (size_t)b * N_DIM;
    float acc[10];
    #pragma unroll
    for (int c = 0; c < 10; c++) acc[c] = 0.0f;
    for (int k = lane; k < N_DIM; k += 32) {
        float s = srow[k];
        #pragma unroll
        for (int c = 0; c < 10; c++)
            acc[c] += s * w2[c * N_DIM + k];
    }
    #pragma unroll
    for (int c = 0; c < 10; c++) {
        float s = acc[c];
        #pragma unroll
        for (int off = 16; off; off >>= 1)
            s += __shfl_xor_sync(0xFFFFFFFFu, s, off);
        if (lane == 0) out[(size_t)b * 10 + c] = s / 25.0f;
    }
}

// ---------------- launch ----------------------------------------------------
extern "C" void kernel_launch(void* const* d_in, const int* in_sizes, int n_in,
                              void* d_out, int out_size) {
    const float* inp = (const float*)d_in[0];   // [8192, 784]
    const float* w1  = (const float*)d_in[1];   // [800, 784]
    const float* w2  = (const float*)d_in[2];   // [10, 800]
    float* out = (float*)d_out;                 // [8192, 10]

    k_init<<<1, 32>>>();
    k_wsplit<<<(N_DIM * K_DIM + 255) / 256, 256>>>(w1);
    k_spike_all<<<dim3(STEP_ELEMS / 16 / 256, NSTEPS), 256>>>(inp);
    k_gemm_f<<<dim3(5, 1600), 256>>>();
    k_lif_flag<<<(Z_STEP / 16 + 255) / 256, 256>>>();
    k_exact<<<512, 256>>>(w1);
    k_final<<<(B_ROWS + 7) / 8, 256>>>(w2, out);
}

// round 15
// speedup vs baseline: 2.0213x; 1.6691x over previous
#include <cuda_runtime.h>
#include <cuda_fp16.h>
#include <cstdint>

#define B_ROWS 8192
#define K_DIM  784
#define N_DIM  800
#define NSTEPS 25
#define STEP_ELEMS (B_ROWS * K_DIM)       // 6422528
#define Z_STEP  (B_ROWS * N_DIM)          // 6553600
#define WL_CAP  (1 << 20)
#define DELTA   1e-4f
#define NIT     98                        // 2 fp16-split passes x 49 k16 tiles
#define STAGES  3
#define NT      160                       // N tile (800 = 5 x 160, no padding)

// ---------------- device scratch ------------------------------------------
__device__ __align__(16) __half    g_sph[(size_t)NSTEPS * STEP_ELEMS];
__device__ uint32_t  g_spc[(size_t)NSTEPS * STEP_ELEMS / 16];   // 2-bit codes
__device__ float     g_Z[(size_t)NSTEPS * Z_STEP];              // fast Z
__device__ float     g_S[Z_STEP];                               // spike counts
__device__ __align__(16) __half    g_w1s[2][(size_t)N_DIM * K_DIM];
__device__ uint2     g_keys[NSTEPS];
__device__ int       g_cnt;
__device__ int       g_wl[WL_CAP];

// ---------------- threefry2x32 (matches JAX, 20 rounds) -------------------
__device__ __forceinline__ void threefry2x32(uint32_t k0, uint32_t k1,
                                             uint32_t x0, uint32_t x1,
                                             uint32_t &o0, uint32_t &o1) {
    uint32_t ks0 = k0, ks1 = k1, ks2 = 0x1BD11BDAu ^ k0 ^ k1;
    x0 += ks0; x1 += ks1;
#define TF_R(r) { x0 += x1; x1 = __funnelshift_l(x1, x1, (r)); x1 ^= x0; }
    TF_R(13) TF_R(15) TF_R(26) TF_R(6)
    x0 += ks1; x1 += ks2 + 1u;
    TF_R(17) TF_R(29) TF_R(16) TF_R(24)
    x0 += ks2; x1 += ks0 + 2u;
    TF_R(13) TF_R(15) TF_R(26) TF_R(6)
    x0 += ks0; x1 += ks1 + 3u;
    TF_R(17) TF_R(29) TF_R(16) TF_R(24)
    x0 += ks1; x1 += ks2 + 4u;
    TF_R(13) TF_R(15) TF_R(26) TF_R(6)
    x0 += ks2; x1 += ks0 + 5u;
#undef TF_R
    o0 = x0; o1 = x1;
}

__global__ void k_init() {
    int t = threadIdx.x;
    if (t < NSTEPS) {
        uint32_t o0, o1;
        threefry2x32(0u, 42u, 0u, (uint32_t)t, o0, o1);
        g_keys[t] = make_uint2(o0, o1);
    }
    if (t == 0) g_cnt = 0;
}

// ---------------- w1 -> 2 fp16 splits (exact power-of-2 scaled) ------------
__global__ void k_wsplit(const float* __restrict__ w1) {
    int idx = blockIdx.x * blockDim.x + threadIdx.x;
    if (idx >= N_DIM * K_DIM) return;
    float w = w1[idx];
    __half h0 = __float2half_rn(w * 512.0f);
    float r1 = w - __half2float(h0) * 0.001953125f;          // w - h0*2^-9
    __half h1 = __float2half_rn(r1 * 1048576.0f);            // * 2^20
    g_w1s[0][idx] = h0;
    g_w1s[1][idx] = h1;
}

// ---------------- spike generation: fp16 + 2-bit codes, 16 elems/thread ----
__global__ void k_spike_all(const float* __restrict__ inp) {
    const int t = blockIdx.y;
    const uint32_t e0 = (blockIdx.x * blockDim.x + threadIdx.x) * 16u;
    if (e0 >= STEP_ELEMS) return;
    const uint2 key = g_keys[t];
    float xv[16];
    #pragma unroll
    for (int v = 0; v < 4; v++)
        *(float4*)&xv[v * 4] = *(const float4*)(inp + e0 + v * 4);
    uint32_t codes = 0;
    __half sb[16];
    #pragma unroll
    for (int c = 0; c < 16; c++) {
        uint32_t o0, o1;
        threefry2x32(key.x, key.y, 0u, e0 + (uint32_t)c, o0, o1);
        uint32_t bits = o0 ^ o1;
        float r = __uint_as_float((bits >> 9) | 0x3f800000u) - 1.0f;
        float x = xv[c];
        uint32_t code = 1u;                          // sp = 0.5
        if (r * 2.0f <= fabsf(x)) {
            if (x > 0.0f)      code = 2u;            // sp = 1
            else if (x < 0.0f) code = 0u;            // sp = 0
        }
        codes |= code << (2 * c);
        unsigned short hb = code ? (unsigned short)(0x3400u + (code << 10)) : 0;
        sb[c] = __ushort_as_half(hb);                // 0 / 0.5 / 1 exact
    }
    size_t base = (size_t)t * STEP_ELEMS + e0;
    *(uint4*)(g_sph + base)     = *(uint4*)&sb[0];
    *(uint4*)(g_sph + base + 8) = *(uint4*)&sb[8];
    g_spc[base >> 4] = codes;
}

// ---------------- fast GEMM: 128M x 160N tiles, cp.async 3-stage -----------
// (unchanged from round 14 — tensor 51.7%, regs 128, 2 blocks/SM)
__device__ __forceinline__ void ldsm_x4(uint32_t* r, uint32_t addr) {
    asm volatile("ldmatrix.sync.aligned.m8n8.x4.shared.b16 {%0,%1,%2,%3}, [%4];"
                 : "=r"(r[0]), "=r"(r[1]), "=r"(r[2]), "=r"(r[3]) : "r"(addr));
}
__device__ __forceinline__ void ldsm_x2(uint32_t* r, uint32_t addr) {
    asm volatile("ldmatrix.sync.aligned.m8n8.x2.shared.b16 {%0,%1}, [%2];"
                 : "=r"(r[0]), "=r"(r[1]) : "r"(addr));
}
__device__ __forceinline__ void mma16816(float* c, const uint32_t* a,
                                         uint32_t b0, uint32_t b1) {
    asm volatile(
        "mma.sync.aligned.m16n8k16.row.col.f32.f16.f16.f32 "
        "{%0,%1,%2,%3},{%4,%5,%6,%7},{%8,%9},{%0,%1,%2,%3};"
        : "+f"(c[0]), "+f"(c[1]), "+f"(c[2]), "+f"(c[3])
        : "r"(a[0]), "r"(a[1]), "r"(a[2]), "r"(a[3]), "r"(b0), "r"(b1));
}
__device__ __forceinline__ void cp16(uint32_t smem_dst, const void* gsrc) {
    asm volatile("cp.async.cg.shared.global [%0], [%1], 16;"
                 :: "r"(smem_dst), "l"(gsrc) : "memory");
}
__device__ __forceinline__ void cp_commit() {
    asm volatile("cp.async.commit_group;" ::: "memory");
}
__device__ __forceinline__ void cp_wait1() {
    asm volatile("cp.async.wait_group 1;" ::: "memory");
}

#define TILE_A_SZ (128 * 48)               // 6144
#define TILE_B_SZ (NT * 48)                // 7680
#define STAGE_SZ  (TILE_A_SZ + TILE_B_SZ)  // 13824

__global__ __launch_bounds__(256, 2) void k_gemm_f() {
    __shared__ __align__(16) char smem[STAGES * STAGE_SZ];   // 41472 B

    const int tid  = threadIdx.x;
    const int bx   = blockIdx.x;               // 0..4  (N, 160 each)
    const int by   = blockIdx.y;               // 0..1599 (M, 128 each)
    const int warp = tid >> 5, lane = tid & 31;
    const int wm = (warp & 1) * 64;
    const int wn = (warp >> 1) * 40;

    const uint32_t sBase = (uint32_t)__cvta_generic_to_shared(smem);

    uint32_t offA[4], offB4[2], offB2;
    {
        int rA = (lane & 7) + ((lane >> 3) & 1) * 8;
        int hA = lane >> 4;
        #pragma unroll
        for (int mi = 0; mi < 4; mi++)
            offA[mi] = (uint32_t)(wm + mi * 16 + rA) * 48 + hA * 16;
        int rB = (lane & 7) + ((lane >> 4) & 1) * 8;
        int hB = (lane >> 3) & 1;
        #pragma unroll
        for (int p = 0; p < 2; p++)
            offB4[p] = TILE_A_SZ + (uint32_t)(wn + p * 16 + rB) * 48 + hB * 16;
        int rB2 = lane & 7;
        int hB2 = (lane >> 3) & 1;
        offB2 = TILE_A_SZ + (uint32_t)(wn + 32 + rB2) * 48 + hB2 * 16;
    }

    const int rowL = tid >> 1;
    const int half = tid & 1;
    const __half* Abase = g_sph + (size_t)(by * 128) * K_DIM
                                + (size_t)rowL * K_DIM + half * 8;
    const int bn = bx * NT;
    const size_t wOff0 = (size_t)(bn + rowL) * K_DIM + half * 8;
    const size_t wOff1 = (size_t)(bn + 128 + rowL) * K_DIM + half * 8;
    const uint32_t dOffA  = (uint32_t)rowL * 48 + half * 16;
    const uint32_t dOffB0 = TILE_A_SZ + (uint32_t)rowL * 48 + half * 16;
    const uint32_t dOffB1 = TILE_A_SZ + (uint32_t)(128 + rowL) * 48 + half * 16;

    float c[4][5][4];
    #pragma unroll
    for (int mi = 0; mi < 4; mi++)
        #pragma unroll
        for (int ni = 0; ni < 5; ni++)
            #pragma unroll
            for (int q = 0; q < 4; q++) c[mi][ni][q] = 0.0f;

    auto issue = [&](int it) {
        const int sel = (it < 49) ? 1 : 0;
        const int kt  = (it < 49) ? it : it - 49;
        const uint32_t st = sBase + (uint32_t)(it % STAGES) * STAGE_SZ;
        cp16(st + dOffA, Abase + kt * 16);
        cp16(st + dOffB0, g_w1s[sel] + wOff0 + kt * 16);
        if (tid < 64)
            cp16(st + dOffB1, g_w1s[sel] + wOff1 + kt * 16);
    };

    issue(0); cp_commit();
    issue(1); cp_commit();

    #pragma unroll 1
    for (int it = 0; it < NIT; it++) {
        cp_wait1();
        __syncthreads();

        const uint32_t sCur = sBase + (uint32_t)(it % STAGES) * STAGE_SZ;
        uint32_t a[4][4], bf[2][4], b2[2];
        #pragma unroll
        for (int mi = 0; mi < 4; mi++) ldsm_x4(a[mi], sCur + offA[mi]);
        #pragma unroll
        for (int p = 0; p < 2; p++)    ldsm_x4(bf[p], sCur + offB4[p]);
        ldsm_x2(b2, sCur + offB2);
        #pragma unroll
        for (int mi = 0; mi < 4; mi++) {
            #pragma unroll
            for (int ni = 0; ni < 4; ni++)
                mma16816(c[mi][ni], a[mi], bf[ni >> 1][(ni & 1) * 2],
                         bf[ni >> 1][(ni & 1) * 2 + 1]);
            mma16816(c[mi][4], a[mi], b2[0], b2[1]);
        }

        if (it == 48) {                  // end of split-1 pass: x2^-11 (exact)
            #pragma unroll
            for (int mi = 0; mi < 4; mi++)
                #pragma unroll
                for (int ni = 0; ni < 5; ni++)
                    #pragma unroll
                    for (int q = 0; q < 4; q++)
                        c[mi][ni][q] *= 4.8828125e-4f;
        }

        if (it + 2 < NIT) issue(it + 2);
        cp_commit();
    }

    const int r0 = by * 128 + wm + (lane >> 2);
    const int cc0 = bn + wn + (lane & 3) * 2;
    #pragma unroll
    for (int mi = 0; mi < 4; mi++)
        #pragma unroll
        for (int ni = 0; ni < 5; ni++) {
            int col = cc0 + ni * 8;
            int row = r0 + mi * 16;
            *(float2*)(g_Z + (size_t)row * N_DIM + col) =
                make_float2(c[mi][ni][0] * 0.001953125f,
                            c[mi][ni][1] * 0.001953125f);
            *(float2*)(g_Z + (size_t)(row + 8) * N_DIM + col) =
                make_float2(c[mi][ni][2] * 0.001953125f,
                            c[mi][ni][3] * 0.001953125f);
        }
}

// ---------------- LIF + flagging: warp-aggregated worklist push -------------
__global__ void k_lif_flag() {
    const int q = blockIdx.x * blockDim.x + threadIdx.x;
    if (q >= Z_STEP / 16) return;
    const int idx = q * 16;
    const int lane = threadIdx.x & 31;
    const float cL = 0.95f;
    const float cI = 0.05000000074505806f;
    float m[16], cnt[16];
    unsigned flag = 0;
    #pragma unroll
    for (int h = 0; h < 16; h++) { m[h] = 0.0f; cnt[h] = 0.0f; }

    float4 z[4];
    #pragma unroll
    for (int v = 0; v < 4; v++)
        z[v] = *(const float4*)(g_Z + idx + v * 4);

    #pragma unroll 1
    for (int t = 0; t < NSTEPS; t++) {
        float4 zn[4];
        if (t + 1 < NSTEPS) {
            #pragma unroll
            for (int v = 0; v < 4; v++)
                zn[v] = *(const float4*)(g_Z + (size_t)(t + 1) * Z_STEP + idx + v * 4);
        }
        #pragma unroll
        for (int v = 0; v < 4; v++) {
            const float* zp = &z[v].x;
            #pragma unroll
            for (int u = 0; u < 4; u++) {
                int h = v * 4 + u;
                m[h] = __fadd_rn(__fmul_rn(cL, m[h]), __fmul_rn(cI, zp[u]));
                float thr = __fadd_rn(m[h], -1.0f);
                if (fabsf(thr) <= DELTA) flag |= 1u << h;
                if (thr > 0.0f) { cnt[h] += 1.0f; m[h] = __fadd_rn(m[h], -1.0f); }
            }
        }
        if (t + 1 < NSTEPS) {
            #pragma unroll
            for (int v = 0; v < 4; v++) z[v] = zn[v];
        }
    }
    #pragma unroll
    for (int v = 0; v < 4; v++)
        *(float4*)(g_S + idx + v * 4) =
            make_float4(cnt[v*4], cnt[v*4+1], cnt[v*4+2], cnt[v*4+3]);

    // warp-aggregated worklist push: ONE atomic per warp
    const unsigned fullm = 0xFFFFFFFFu;
    int my = __popc(flag);
    int incl = my;
    #pragma unroll
    for (int d = 1; d < 32; d <<= 1) {
        int v = __shfl_up_sync(fullm, incl, d);
        if (lane >= d) incl += v;
    }
    int tot = __shfl_sync(fullm, incl, 31);
    int excl = incl - my;
    int base = 0;
    if (lane == 31 && tot > 0) base = atomicAdd(&g_cnt, tot);
    base = __shfl_sync(fullm, base, 31);
    int pos = base + excl;
    while (flag) {
        int h = __ffs(flag) - 1;
        flag &= flag - 1;
        if (pos < WL_CAP) g_wl[pos] = idx + h;
        pos++;
    }
}

// ---------------- exact recompute: one WARP per flagged element -------------
// Lane t (t < 25) computes step-t csum with the IDENTICAL Eigen 4-panel
// ascending-k chain; lane 0 then runs the LIF recurrence over shuffled csums.
__global__ void k_exact(const float* __restrict__ w1) {
    int n = g_cnt; if (n > WL_CAP) n = WL_CAP;
    const int lane = threadIdx.x & 31;
    const int gw = (blockIdx.x * blockDim.x + threadIdx.x) >> 5;
    const int nwarps = (gridDim.x * blockDim.x) >> 5;
    const float cL = 0.95f;
    const float cI = 0.05000000074505806f;
    for (int i = gw; i < n; i += nwarps) {
        const int e = g_wl[i];
        const int b = e / N_DIM, j = e % N_DIM;
        const float* wrow = w1 + (size_t)j * K_DIM;
        float csum = 0.0f;
        if (lane < NSTEPS) {
            const uint32_t* cw = g_spc +
                (((size_t)lane * STEP_ELEMS + (size_t)b * K_DIM) >> 4);
            const int pend[4] = {248, 496, 744, 784};
            int k = 0;
            #pragma unroll 1
            for (int p = 0; p < 4; p++) {
                float acc = 0.0f;
                #pragma unroll 4
                for (; k < pend[p]; k++) {
                    uint32_t code = (cw[k >> 4] >> ((k & 15) * 2)) & 3u;
                    float sp = 0.5f * (float)code;
                    acc = __fmaf_rn(sp, wrow[k], acc);
                }
                csum = __fadd_rn(csum, acc);
            }
        }
        float m = 0.0f, cnt = 0.0f;
        #pragma unroll 1
        for (int t = 0; t < NSTEPS; t++) {
            float cs = __shfl_sync(0xFFFFFFFFu, csum, t);
            if (lane == 0) {
                m = __fadd_rn(__fmul_rn(cL, m), __fmul_rn(cI, cs));
                float thr = __fadd_rn(m, -1.0f);
                if (thr > 0.0f) { cnt += 1.0f; m = __fadd_rn(m, -1.0f); }
            }
        }
        if (lane == 0) g_S[e] = cnt;
    }
}

// ---------------- final: one warp per row, all 10 classes -------------------
__global__ void k_final(const float* __restrict__ w2, float* __restrict__ out) {
    int b    = (blockIdx.x * blockDim.x + threadIdx.x) >> 5;
    int lane = threadIdx.x & 31;
    if (b >= B_ROWS) return;
    const float* srow = g_S + (size_t)b * N_DIM;
    float acc[10];
    #pragma unroll
    for (int c = 0; c < 10; c++) acc[c] = 0.0f;
    for (int k = lane; k < N_DIM; k += 32) {
        float s = srow[k];
        #pragma unroll
        for (int c = 0; c < 10; c++)
            acc[c] += s * w2[c * N_DIM + k];
    }
    #pragma unroll
    for (int c = 0; c < 10; c++) {
        float s = acc[c];
        #pragma unroll
        for (int off = 16; off; off >>= 1)
            s += __shfl_xor_sync(0xFFFFFFFFu, s, off);
        if (lane == 0) out[(size_t)b * 10 + c] = s / 25.0f;
    }
}

// ---------------- launch ----------------------------------------------------
// NOTE: launch order places k_spike_all 4th — the slot the profiler captures —
// to obtain its first direct measurement. k_init is idempotent.
extern "C" void kernel_launch(void* const* d_in, const int* in_sizes, int n_in,
                              void* d_out, int out_size) {
    const float* inp = (const float*)d_in[0];   // [8192, 784]
    const float* w1  = (const float*)d_in[1];   // [800, 784]
    const float* w2  = (const float*)d_in[2];   // [10, 800]
    float* out = (float*)d_out;                 // [8192, 10]

    k_init<<<1, 32>>>();                                        // 1
    k_wsplit<<<(N_DIM * K_DIM + 255) / 256, 256>>>(w1);         // 2
    k_init<<<1, 32>>>();                                        // 3 (dummy)
    k_spike_all<<<dim3(STEP_ELEMS / 16 / 256, NSTEPS), 256>>>(inp);  // 4 ← profiled
    k_gemm_f<<<dim3(5, 1600), 256>>>();                         // 5
    k_lif_flag<<<(Z_STEP / 16 + 255) / 256, 256>>>();           // 6
    k_exact<<<512, 256>>>(w1);                                  // 7
    k_final<<<(B_ROWS + 7) / 8, 256>>>(w2, out);                // 8
}

// round 16
// speedup vs baseline: 2.1075x; 1.0426x over previous
#include <cuda_runtime.h>
#include <cuda_fp16.h>
#include <cstdint>

#define B_ROWS 8192
#define K_DIM  784
#define N_DIM  800
#define NSTEPS 25
#define STEP_ELEMS (B_ROWS * K_DIM)       // 6422528
#define Z_STEP  (B_ROWS * N_DIM)          // 6553600
#define WL_CAP  (1 << 20)
#define DELTA   1e-4f
#define NIT     98                        // 2 fp16-split passes x 49 k16 tiles
#define STAGES  6                         // k16-tile stages (2 computed/barrier)
#define NT      160                       // N tile (800 = 5 x 160, no padding)

// ---------------- device scratch ------------------------------------------
__device__ __align__(16) __half    g_sph[(size_t)NSTEPS * STEP_ELEMS];
__device__ uint32_t  g_spc[(size_t)NSTEPS * STEP_ELEMS / 16];   // 2-bit codes
__device__ float     g_Z[(size_t)NSTEPS * Z_STEP];              // fast Z
__device__ float     g_S[Z_STEP];                               // spike counts
__device__ __align__(16) __half    g_w1s[2][(size_t)N_DIM * K_DIM];
__device__ uint2     g_keys[NSTEPS];
__device__ int       g_cnt;
__device__ int       g_wl[WL_CAP];

// ---------------- threefry2x32 (matches JAX, 20 rounds) -------------------
__device__ __forceinline__ void threefry2x32(uint32_t k0, uint32_t k1,
                                             uint32_t x0, uint32_t x1,
                                             uint32_t &o0, uint32_t &o1) {
    uint32_t ks0 = k0, ks1 = k1, ks2 = 0x1BD11BDAu ^ k0 ^ k1;
    x0 += ks0; x1 += ks1;
#define TF_R(r) { x0 += x1; x1 = __funnelshift_l(x1, x1, (r)); x1 ^= x0; }
    TF_R(13) TF_R(15) TF_R(26) TF_R(6)
    x0 += ks1; x1 += ks2 + 1u;
    TF_R(17) TF_R(29) TF_R(16) TF_R(24)
    x0 += ks2; x1 += ks0 + 2u;
    TF_R(13) TF_R(15) TF_R(26) TF_R(6)
    x0 += ks0; x1 += ks1 + 3u;
    TF_R(17) TF_R(29) TF_R(16) TF_R(24)
    x0 += ks1; x1 += ks2 + 4u;
    TF_R(13) TF_R(15) TF_R(26) TF_R(6)
    x0 += ks2; x1 += ks0 + 5u;
#undef TF_R
    o0 = x0; o1 = x1;
}

__global__ void k_init() {
    int t = threadIdx.x;
    if (t < NSTEPS) {
        uint32_t o0, o1;
        threefry2x32(0u, 42u, 0u, (uint32_t)t, o0, o1);
        g_keys[t] = make_uint2(o0, o1);
    }
    if (t == 0) g_cnt = 0;
}

// ---------------- w1 -> 2 fp16 splits (exact power-of-2 scaled) ------------
__global__ void k_wsplit(const float* __restrict__ w1) {
    int idx = blockIdx.x * blockDim.x + threadIdx.x;
    if (idx >= N_DIM * K_DIM) return;
    float w = w1[idx];
    __half h0 = __float2half_rn(w * 512.0f);
    float r1 = w - __half2float(h0) * 0.001953125f;          // w - h0*2^-9
    __half h1 = __float2half_rn(r1 * 1048576.0f);            // * 2^20
    g_w1s[0][idx] = h0;
    g_w1s[1][idx] = h1;
}

// ---------------- spike generation: fp16 + 2-bit codes, 16 elems/thread ----
__global__ void k_spike_all(const float* __restrict__ inp) {
    const int t = blockIdx.y;
    const uint32_t e0 = (blockIdx.x * blockDim.x + threadIdx.x) * 16u;
    if (e0 >= STEP_ELEMS) return;
    const uint2 key = g_keys[t];
    float xv[16];
    #pragma unroll
    for (int v = 0; v < 4; v++)
        *(float4*)&xv[v * 4] = *(const float4*)(inp + e0 + v * 4);
    uint32_t codes = 0;
    __half sb[16];
    #pragma unroll
    for (int c = 0; c < 16; c++) {
        uint32_t o0, o1;
        threefry2x32(key.x, key.y, 0u, e0 + (uint32_t)c, o0, o1);
        uint32_t bits = o0 ^ o1;
        float r = __uint_as_float((bits >> 9) | 0x3f800000u) - 1.0f;
        float x = xv[c];
        uint32_t code = 1u;                          // sp = 0.5
        if (r * 2.0f <= fabsf(x)) {
            if (x > 0.0f)      code = 2u;            // sp = 1
            else if (x < 0.0f) code = 0u;            // sp = 0
        }
        codes |= code << (2 * c);
        unsigned short hb = code ? (unsigned short)(0x3400u + (code << 10)) : 0;
        sb[c] = __ushort_as_half(hb);                // 0 / 0.5 / 1 exact
    }
    size_t base = (size_t)t * STEP_ELEMS + e0;
    *(uint4*)(g_sph + base)     = *(uint4*)&sb[0];
    *(uint4*)(g_sph + base + 8) = *(uint4*)&sb[8];
    g_spc[base >> 4] = codes;
}

// ---------------- fast GEMM: 128M x 160N, 6-stage ring, 2 tiles/barrier ----
__device__ __forceinline__ void ldsm_x4(uint32_t* r, uint32_t addr) {
    asm volatile("ldmatrix.sync.aligned.m8n8.x4.shared.b16 {%0,%1,%2,%3}, [%4];"
                 : "=r"(r[0]), "=r"(r[1]), "=r"(r[2]), "=r"(r[3]) : "r"(addr));
}
__device__ __forceinline__ void ldsm_x2(uint32_t* r, uint32_t addr) {
    asm volatile("ldmatrix.sync.aligned.m8n8.x2.shared.b16 {%0,%1}, [%2];"
                 : "=r"(r[0]), "=r"(r[1]) : "r"(addr));
}
__device__ __forceinline__ void mma16816(float* c, const uint32_t* a,
                                         uint32_t b0, uint32_t b1) {
    asm volatile(
        "mma.sync.aligned.m16n8k16.row.col.f32.f16.f16.f32 "
        "{%0,%1,%2,%3},{%4,%5,%6,%7},{%8,%9},{%0,%1,%2,%3};"
        : "+f"(c[0]), "+f"(c[1]), "+f"(c[2]), "+f"(c[3])
        : "r"(a[0]), "r"(a[1]), "r"(a[2]), "r"(a[3]), "r"(b0), "r"(b1));
}
__device__ __forceinline__ void cp16(uint32_t smem_dst, const void* gsrc) {
    asm volatile("cp.async.cg.shared.global [%0], [%1], 16;"
                 :: "r"(smem_dst), "l"(gsrc) : "memory");
}
__device__ __forceinline__ void cp_commit() {
    asm volatile("cp.async.commit_group;" ::: "memory");
}
__device__ __forceinline__ void cp_wait2() {
    asm volatile("cp.async.wait_group 2;" ::: "memory");
}

#define TILE_A_SZ (128 * 48)               // 6144
#define TILE_B_SZ (NT * 48)                // 7680
#define STAGE_SZ  (TILE_A_SZ + TILE_B_SZ)  // 13824
#define SMEM_DYN  (STAGES * STAGE_SZ)      // 82944

__global__ __launch_bounds__(256, 2) void k_gemm_f() {
    extern __shared__ __align__(16) char smem[];

    const int tid  = threadIdx.x;
    const int bx   = blockIdx.x;               // 0..4  (N, 160 each)
    const int by   = blockIdx.y;               // 0..1599 (M, 128 each)
    const int warp = tid >> 5, lane = tid & 31;
    const int wm = (warp & 1) * 64;
    const int wn = (warp >> 1) * 40;

    const uint32_t sBase = (uint32_t)__cvta_generic_to_shared(smem);

    uint32_t offA[4], offB4[2], offB2;
    {
        int rA = (lane & 7) + ((lane >> 3) & 1) * 8;
        int hA = lane >> 4;
        #pragma unroll
        for (int mi = 0; mi < 4; mi++)
            offA[mi] = (uint32_t)(wm + mi * 16 + rA) * 48 + hA * 16;
        int rB = (lane & 7) + ((lane >> 4) & 1) * 8;
        int hB = (lane >> 3) & 1;
        #pragma unroll
        for (int p = 0; p < 2; p++)
            offB4[p] = TILE_A_SZ + (uint32_t)(wn + p * 16 + rB) * 48 + hB * 16;
        int rB2 = lane & 7;
        int hB2 = (lane >> 3) & 1;
        offB2 = TILE_A_SZ + (uint32_t)(wn + 32 + rB2) * 48 + hB2 * 16;
    }

    const int rowL = tid >> 1;
    const int half = tid & 1;
    const __half* Abase = g_sph + (size_t)(by * 128) * K_DIM
                                + (size_t)rowL * K_DIM + half * 8;
    const int bn = bx * NT;
    const size_t wOff0 = (size_t)(bn + rowL) * K_DIM + half * 8;
    const size_t wOff1 = (size_t)(bn + 128 + rowL) * K_DIM + half * 8;
    const uint32_t dOffA  = (uint32_t)rowL * 48 + half * 16;
    const uint32_t dOffB0 = TILE_A_SZ + (uint32_t)rowL * 48 + half * 16;
    const uint32_t dOffB1 = TILE_A_SZ + (uint32_t)(128 + rowL) * 48 + half * 16;

    float c[4][5][4];
    #pragma unroll
    for (int mi = 0; mi < 4; mi++)
        #pragma unroll
        for (int ni = 0; ni < 5; ni++)
            #pragma unroll
            for (int q = 0; q < 4; q++) c[mi][ni][q] = 0.0f;

    auto issue = [&](int it) {
        const int sel = (it < 49) ? 1 : 0;
        const int kt  = (it < 49) ? it : it - 49;
        const uint32_t st = sBase + (uint32_t)(it % STAGES) * STAGE_SZ;
        cp16(st + dOffA, Abase + kt * 16);
        cp16(st + dOffB0, g_w1s[sel] + wOff0 + kt * 16);
        if (tid < 64)
            cp16(st + dOffB1, g_w1s[sel] + wOff1 + kt * 16);
    };

    auto compute = [&](int it) {
        const uint32_t sCur = sBase + (uint32_t)(it % STAGES) * STAGE_SZ;
        uint32_t a[4][4], bf[2][4], b2[2];
        #pragma unroll
        for (int mi = 0; mi < 4; mi++) ldsm_x4(a[mi], sCur + offA[mi]);
        #pragma unroll
        for (int p = 0; p < 2; p++)    ldsm_x4(bf[p], sCur + offB4[p]);
        ldsm_x2(b2, sCur + offB2);
        #pragma unroll
        for (int mi = 0; mi < 4; mi++) {
            #pragma unroll
            for (int ni = 0; ni < 4; ni++)
                mma16816(c[mi][ni], a[mi], bf[ni >> 1][(ni & 1) * 2],
                         bf[ni >> 1][(ni & 1) * 2 + 1]);
            mma16816(c[mi][4], a[mi], b2[0], b2[1]);
        }
        if (it == 48) {                  // end of split-1 pass: x2^-11 (exact)
            #pragma unroll
            for (int mi = 0; mi < 4; mi++)
                #pragma unroll
                for (int ni = 0; ni < 5; ni++)
                    #pragma unroll
                    for (int q = 0; q < 4; q++)
                        c[mi][ni][q] *= 4.8828125e-4f;
        }
    };

    // prologue: 4 tiles in flight
    issue(0); cp_commit();
    issue(1); cp_commit();
    issue(2); cp_commit();
    issue(3); cp_commit();

    #pragma unroll 1
    for (int it = 0; it < NIT; it += 2) {
        cp_wait2();                      // tiles it, it+1 complete (2 pending)
        __syncthreads();

        compute(it);
        compute(it + 1);

        // issue tiles it+4, it+5 — their stages were computed LAST iteration,
        // protected by this iteration's barrier (R13 discipline, pair form)
        if (it + 4 < NIT) issue(it + 4);
        cp_commit();
        if (it + 5 < NIT) issue(it + 5);
        cp_commit();
    }

    // store Z = 2^-9 * c  (no guards: 5*160 = 800 exactly)
    const int r0 = by * 128 + wm + (lane >> 2);
    const int cc0 = bn + wn + (lane & 3) * 2;
    #pragma unroll
    for (int mi = 0; mi < 4; mi++)
        #pragma unroll
        for (int ni = 0; ni < 5; ni++) {
            int col = cc0 + ni * 8;
            int row = r0 + mi * 16;
            *(float2*)(g_Z + (size_t)row * N_DIM + col) =
                make_float2(c[mi][ni][0] * 0.001953125f,
                            c[mi][ni][1] * 0.001953125f);
            *(float2*)(g_Z + (size_t)(row + 8) * N_DIM + col) =
                make_float2(c[mi][ni][2] * 0.001953125f,
                            c[mi][ni][3] * 0.001953125f);
        }
}

// ---------------- LIF + flagging: warp-aggregated worklist push -------------
__global__ void k_lif_flag() {
    const int q = blockIdx.x * blockDim.x + threadIdx.x;
    if (q >= Z_STEP / 16) return;
    const int idx = q * 16;
    const int lane = threadIdx.x & 31;
    const float cL = 0.95f;
    const float cI = 0.05000000074505806f;
    float m[16], cnt[16];
    unsigned flag = 0;
    #pragma unroll
    for (int h = 0; h < 16; h++) { m[h] = 0.0f; cnt[h] = 0.0f; }

    float4 z[4];
    #pragma unroll
    for (int v = 0; v < 4; v++)
        z[v] = *(const float4*)(g_Z + idx + v * 4);

    #pragma unroll 1
    for (int t = 0; t < NSTEPS; t++) {
        float4 zn[4];
        if (t + 1 < NSTEPS) {
            #pragma unroll
            for (int v = 0; v < 4; v++)
                zn[v] = *(const float4*)(g_Z + (size_t)(t + 1) * Z_STEP + idx + v * 4);
        }
        #pragma unroll
        for (int v = 0; v < 4; v++) {
            const float* zp = &z[v].x;
            #pragma unroll
            for (int u = 0; u < 4; u++) {
                int h = v * 4 + u;
                m[h] = __fadd_rn(__fmul_rn(cL, m[h]), __fmul_rn(cI, zp[u]));
                float thr = __fadd_rn(m[h], -1.0f);
                if (fabsf(thr) <= DELTA) flag |= 1u << h;
                if (thr > 0.0f) { cnt[h] += 1.0f; m[h] = __fadd_rn(m[h], -1.0f); }
            }
        }
        if (t + 1 < NSTEPS) {
            #pragma unroll
            for (int v = 0; v < 4; v++) z[v] = zn[v];
        }
    }
    #pragma unroll
    for (int v = 0; v < 4; v++)
        *(float4*)(g_S + idx + v * 4) =
            make_float4(cnt[v*4], cnt[v*4+1], cnt[v*4+2], cnt[v*4+3]);

    // warp-aggregated worklist push: ONE atomic per warp
    const unsigned fullm = 0xFFFFFFFFu;
    int my = __popc(flag);
    int incl = my;
    #pragma unroll
    for (int d = 1; d < 32; d <<= 1) {
        int v = __shfl_up_sync(fullm, incl, d);
        if (lane >= d) incl += v;
    }
    int tot = __shfl_sync(fullm, incl, 31);
    int excl = incl - my;
    int base = 0;
    if (lane == 31 && tot > 0) base = atomicAdd(&g_cnt, tot);
    base = __shfl_sync(fullm, base, 31);
    int pos = base + excl;
    while (flag) {
        int h = __ffs(flag) - 1;
        flag &= flag - 1;
        if (pos < WL_CAP) g_wl[pos] = idx + h;
        pos++;
    }
}

// ---------------- exact recompute: one WARP per flagged element -------------
__global__ void k_exact(const float* __restrict__ w1) {
    int n = g_cnt; if (n > WL_CAP) n = WL_CAP;
    const int lane = threadIdx.x & 31;
    const int gw = (blockIdx.x * blockDim.x + threadIdx.x) >> 5;
    const int nwarps = (gridDim.x * blockDim.x) >> 5;
    const float cL = 0.95f;
    const float cI = 0.05000000074505806f;
    for (int i = gw; i < n; i += nwarps) {
        const int e = g_wl[i];
        const int b = e / N_DIM, j = e % N_DIM;
        const float* wrow = w1 + (size_t)j * K_DIM;
        float csum = 0.0f;
        if (lane < NSTEPS) {
            const uint32_t* cw = g_spc +
                (((size_t)lane * STEP_ELEMS + (size_t)b * K_DIM) >> 4);
            const int pend[4] = {248, 496, 744, 784};
            int k = 0;
            #pragma unroll 1
            for (int p = 0; p < 4; p++) {
                float acc = 0.0f;
                #pragma unroll 4
                for (; k < pend[p]; k++) {
                    uint32_t code = (cw[k >> 4] >> ((k & 15) * 2)) & 3u;
                    float sp = 0.5f * (float)code;
                    acc = __fmaf_rn(sp, wrow[k], acc);
                }
                csum = __fadd_rn(csum, acc);
            }
        }
        float m = 0.0f, cnt = 0.0f;
        #pragma unroll 1
        for (int t = 0; t < NSTEPS; t++) {
            float cs = __shfl_sync(0xFFFFFFFFu, csum, t);
            if (lane == 0) {
                m = __fadd_rn(__fmul_rn(cL, m), __fmul_rn(cI, cs));
                float thr = __fadd_rn(m, -1.0f);
                if (thr > 0.0f) { cnt += 1.0f; m = __fadd_rn(m, -1.0f); }
            }
        }
        if (lane == 0) g_S[e] = cnt;
    }
}

// ---------------- final: one warp per row, all 10 classes -------------------
__global__ void k_final(const float* __restrict__ w2, float* __restrict__ out) {
    int b    = (blockIdx.x * blockDim.x + threadIdx.x) >> 5;
    int lane = threadIdx.x & 31;
    if (b >= B_ROWS) return;
    const float* srow = g_S + (size_t)b * N_DIM;
    float acc[10];
    #pragma unroll
    for (int c = 0; c < 10; c++) acc[c] = 0.0f;
    for (int k = lane; k < N_DIM; k += 32) {
        float s = srow[k];
        #pragma unroll
        for (int c = 0; c < 10; c++)
            acc[c] += s * w2[c * N_DIM + k];
    }
    #pragma unroll
    for (int c = 0; c < 10; c++) {
        float s = acc[c];
        #pragma unroll
        for (int off = 16; off; off >>= 1)
            s += __shfl_xor_sync(0xFFFFFFFFu, s, off);
        if (lane == 0) out[(size_t)b * 10 + c] = s / 25.0f;
    }
}

// ---------------- launch ----------------------------------------------------
extern "C" void kernel_launch(void* const* d_in, const int* in_sizes, int n_in,
                              void* d_out, int out_size) {
    const float* inp = (const float*)d_in[0];   // [8192, 784]
    const float* w1  = (const float*)d_in[1];   // [800, 784]
    const float* w2  = (const float*)d_in[2];   // [10, 800]
    float* out = (float*)d_out;                 // [8192, 10]

    // persistent, allocation-free attribute set (idempotent each call)
    cudaFuncSetAttribute(k_gemm_f,
                         cudaFuncAttributeMaxDynamicSharedMemorySize, SMEM_DYN);

    k_init<<<1, 32>>>();                                        // 1
    k_wsplit<<<(N_DIM * K_DIM + 255) / 256, 256>>>(w1);         // 2
    k_spike_all<<<dim3(STEP_ELEMS / 16 / 256, NSTEPS), 256>>>(inp);  // 3
    k_gemm_f<<<dim3(5, 1600), 256, SMEM_DYN>>>();               // 4 ← profiled
    k_lif_flag<<<(Z_STEP / 16 + 255) / 256, 256>>>();           // 5
    k_exact<<<512, 256>>>(w1);                                  // 6
    k_final<<<(B_ROWS + 7) / 8, 256>>>(w2, out);                // 7
}